// round 11
// baseline (speedup 1.0000x reference)
#include <cuda_runtime.h>
#include <cstdint>

// ---------------- problem constants ----------------
#define Bb    32
#define Tt    128
#define Pp    512
#define MAXL  7
#define Dd    300
#define KSEG  320            // per-segment K (>=300, mult of 32 for int8 k32)
#define KQ    (6*KSEG)       // 1920 int8 K: [h | h,m | h,l,m]
#define Nn    7168
#define Mm    4096
#define NCc   2
#define NEGV  (-1e30f)

// gemm tiling: CTA 128(M) x 128(N), 8 warps (2M x 4N), warp tile 64x32, BK=64 (int8)
#define TILE_M 128
#define TILE_N 128
#define BK    64
#define NKT   (KQ/BK)        // 30
#define NSTG  4
#define ROWB  80             // 64 B data + 16 pad -> conflict-free ldmatrix
#define STAGE_A   (TILE_M*ROWB)               // 10240
#define STAGE_SZ  ((TILE_M+TILE_N)*ROWB)      // 20480
#define SMEM_GEMM (NSTG*STAGE_SZ)             // 81920
#define CPT 4    // cp.async 16B tasks per thread per stage: 256 rows x 4 / 256 thr

// ---------------- scratch ----------------
__device__ signed char g_Aq[(size_t)Mm * KQ];   // compacted rows
__device__ signed char g_Bq[(size_t)Nn * KQ];
__device__ float g_sA[Mm];
__device__ float g_sB[Nn];
__device__ float g_ts[(size_t)Mm * Nn];
__device__ float g_scores[Bb * Pp];
__device__ int   g_off[Bb + 1];
__device__ int   g_padTo;

// ---------------- PTX helpers ----------------
__device__ __forceinline__ void cpasync16(uint32_t s, const void* g){
    asm volatile("cp.async.cg.shared.global [%0], [%1], 16;" :: "r"(s), "l"(g));
}
__device__ __forceinline__ void cp_commit(){
    asm volatile("cp.async.commit_group;" ::: "memory");
}
template<int N> __device__ __forceinline__ void cp_wait(){
    asm volatile("cp.async.wait_group %0;" :: "n"(N) : "memory");
}
__device__ __forceinline__ void ldsm4(uint32_t a, uint32_t& r0, uint32_t& r1, uint32_t& r2, uint32_t& r3){
    asm volatile("ldmatrix.sync.aligned.m8n8.x4.shared.b16 {%0,%1,%2,%3}, [%4];"
                 : "=r"(r0), "=r"(r1), "=r"(r2), "=r"(r3) : "r"(a));
}
__device__ __forceinline__ void mma_s8(int* c, uint32_t a0, uint32_t a1, uint32_t a2, uint32_t a3,
                                       uint32_t b0, uint32_t b1){
    asm volatile("mma.sync.aligned.m16n8k32.row.col.s32.s8.s8.s32 "
                 "{%0,%1,%2,%3}, {%4,%5,%6,%7}, {%8,%9}, {%0,%1,%2,%3};"
                 : "+r"(c[0]), "+r"(c[1]), "+r"(c[2]), "+r"(c[3])
                 : "r"(a0), "r"(a1), "r"(a2), "r"(a3), "r"(b0), "r"(b1));
}

// ---------------- 0. doc-length prefix offsets ----------------
__global__ void offsets_kernel(const int* __restrict__ doc_lens){
    if (threadIdx.x == 0){
        int acc = 0;
        for (int b = 0; b < Bb; b++){ g_off[b] = acc; acc += doc_lens[b]; }
        g_off[Bb] = acc;
        g_padTo = (acc + TILE_M - 1) & ~(TILE_M - 1);
    }
}

// ---------------- quantization helper ----------------
// x = S*(h*2^14 + m*2^7 + l), h in [-127,127], m,l in [-64,64]
__device__ __forceinline__ void quant3(float x, float inv, signed char& h, signed char& m, signed char& l){
    float q = x * inv;
    float hf = rintf(q * (1.0f/16384.0f));
    float r  = q - hf * 16384.0f;
    float mf = rintf(r * (1.0f/128.0f));
    float lf = rintf(r - mf * 128.0f);
    h = (signed char)(int)hf;  m = (signed char)(int)mf;  l = (signed char)(int)lf;
}

__device__ __forceinline__ float block_rowmax(const float* src, int tid, float* wmax){
    float mx = 0.0f;
    for (int k = tid; k < Dd; k += 128) mx = fmaxf(mx, fabsf(src[k]));
    #pragma unroll
    for (int off = 16; off > 0; off >>= 1)
        mx = fmaxf(mx, __shfl_xor_sync(0xffffffffu, mx, off));
    if ((tid & 31) == 0) wmax[tid >> 5] = mx;
    __syncthreads();
    float m0 = fmaxf(fmaxf(wmax[0], wmax[1]), fmaxf(wmax[2], wmax[3]));
    return fmaxf(m0, 1e-20f);
}

// ---------------- 1. quantize A (gathered embeddings, compacted) ----------------
// A row layout: [h(0:320) | h(320:640) m(640:960) | h(960:1280) l(1280:1600) m(1600:1920)]
__global__ void convA_kernel(const int* __restrict__ tokens, const float* __restrict__ emb,
                             const int* __restrict__ doc_lens){
    __shared__ float wmax[4];
    int b = blockIdx.x >> 7, t = blockIdx.x & 127;
    if (t >= doc_lens[b]) return;
    int mrow = g_off[b] + t;
    int tok = tokens[blockIdx.x];
    const float* src = emb + (size_t)tok * Dd;
    int tid = threadIdx.x;

    float rowmax = block_rowmax(src, tid, wmax);
    float S   = rowmax * (1.0f/(127.0f*16384.0f));
    float inv = 1.0f / S;

    signed char* row = g_Aq + (size_t)mrow * KQ;
    for (int k = tid; k < KSEG; k += 128){
        float x = (k < Dd) ? src[k] : 0.0f;
        signed char h, m, l;
        quant3(x, inv, h, m, l);
        row[k] = h;  row[320 + k] = h;  row[960 + k] = h;
        row[640 + k] = m;  row[1600 + k] = m;
        row[1280 + k] = l;
    }
    if (tid == 0) g_sA[mrow] = S;
}

// ---------------- 2. quantize B (diags) ----------------
// B row layout: [h(0:320) | m(320:640) h(640:960) | l(960:1280) h(1280:1600) m(1600:1920)]
__global__ void convB_kernel(const float* __restrict__ diags){
    __shared__ float wmax[4];
    int n = blockIdx.x;
    const float* src = diags + (size_t)n * Dd;
    int tid = threadIdx.x;

    float rowmax = block_rowmax(src, tid, wmax);
    float S   = rowmax * (1.0f/(127.0f*16384.0f));
    float inv = 1.0f / S;

    signed char* row = g_Bq + (size_t)n * KQ;
    for (int k = tid; k < KSEG; k += 128){
        float x = (k < Dd) ? src[k] : 0.0f;
        signed char h, m, l;
        quant3(x, inv, h, m, l);
        row[k] = h;  row[640 + k] = h;  row[1280 + k] = h;
        row[320 + k] = m;  row[1600 + k] = m;
        row[960 + k] = l;
    }
    if (tid == 0) g_sB[n] = S;
}

// ---------------- 3. int8 mma.sync GEMM, 3-phase fixed-point ----------------
// phase kts: [0,5) = h*h ; [5,15) = h*m + m*h ; [15,30) = h*l + l*h + m*m
// F = ((I1*128) + I2)*128 + I3 ;  true bracket = F * 2^14
// ts = F * 16384 * sA * sB + bias
__global__ __launch_bounds__(256, 1) void gemm_kernel(const float* __restrict__ bias)
{
    const int blockM = blockIdx.y * TILE_M;
    if (blockM >= g_padTo) return;

    extern __shared__ char smem[];
    const uint32_t sb = (uint32_t)__cvta_generic_to_shared(smem);
    const int tid = threadIdx.x;
    const int lane = tid & 31, wid = tid >> 5;
    const int wm = wid & 1, wn = wid >> 1;     // 2M x 4N
    const int blockN = blockIdx.x * TILE_N;

    const signed char* gA = g_Aq + (size_t)blockM * KQ;
    const signed char* gB = g_Bq + (size_t)blockN * KQ;

    // cp.async: 4 tasks of 16B per thread (256 rows x 4 chunks)
    uint32_t t_soff[CPT];
    const signed char* t_gptr[CPT];
    #pragma unroll
    for (int q = 0; q < CPT; q++){
        int id = tid + q*256;
        int row = id >> 2, ch = id & 3;
        int isB = (row >= TILE_M);
        int r2  = isB ? (row - TILE_M) : row;
        t_soff[q] = (isB ? STAGE_A : 0) + r2*ROWB + ch*16;
        t_gptr[q] = (isB ? gB : gA) + (size_t)r2 * KQ + ch*16;
    }

    // ldmatrix bases (element = byte; 32-B k-step rows, 16-B chunks)
    const uint32_t aBase = sb + (wm*64 + (lane & 15)) * ROWB + (lane >> 4) * 16;
    const uint32_t bBase = sb + STAGE_A + (wn*32 + ((lane >> 4) << 3) + (lane & 7)) * ROWB
                              + (((lane >> 3) & 1) * 16);

    int   iacc[4][4][4];
    float facc[4][4][4];
    #pragma unroll
    for (int i = 0; i < 4; i++)
        #pragma unroll
        for (int j = 0; j < 4; j++)
            #pragma unroll
            for (int r = 0; r < 4; r++){ iacc[i][j][r] = 0; facc[i][j][r] = 0.0f; }

    // prologue
    #pragma unroll
    for (int s = 0; s < NSTG-1; s++){
        #pragma unroll
        for (int q = 0; q < CPT; q++)
            cpasync16(sb + s*STAGE_SZ + t_soff[q], t_gptr[q] + s*BK);
        cp_commit();
    }

    uint32_t a[2][4][4], b[2][4][2];

    for (int kt = 0; kt < NKT; kt++){
        cp_wait<NSTG-2>();
        __syncthreads();
        const uint32_t stage = (kt % NSTG) * STAGE_SZ;

        // k-step 0 fragments -> buffer 0
        #pragma unroll
        for (int i = 0; i < 4; i++)
            ldsm4(aBase + stage + i*16*ROWB, a[0][i][0], a[0][i][1], a[0][i][2], a[0][i][3]);
        #pragma unroll
        for (int j2 = 0; j2 < 2; j2++){
            uint32_t r0, r1, r2, r3;
            ldsm4(bBase + stage + j2*16*ROWB, r0, r1, r2, r3);
            b[0][2*j2][0] = r0;   b[0][2*j2][1] = r1;
            b[0][2*j2+1][0] = r2; b[0][2*j2+1][1] = r3;
        }

        int nkt = kt + NSTG - 1;
        if (nkt < NKT){
            uint32_t stb = sb + (nkt % NSTG)*STAGE_SZ;
            #pragma unroll
            for (int q = 0; q < CPT; q++)
                cpasync16(stb + t_soff[q], t_gptr[q] + nkt*BK);
        }
        cp_commit();

        // 2 k-steps of 32, double-buffered fragments
        #pragma unroll
        for (int s = 0; s < 2; s++){
            const int cur = s & 1, nxt = cur ^ 1;
            if (s < 1){
                #pragma unroll
                for (int i = 0; i < 4; i++)
                    ldsm4(aBase + stage + i*16*ROWB + 32,
                          a[nxt][i][0], a[nxt][i][1], a[nxt][i][2], a[nxt][i][3]);
                #pragma unroll
                for (int j2 = 0; j2 < 2; j2++){
                    uint32_t r0, r1, r2, r3;
                    ldsm4(bBase + stage + j2*16*ROWB + 32, r0, r1, r2, r3);
                    b[nxt][2*j2][0] = r0;   b[nxt][2*j2][1] = r1;
                    b[nxt][2*j2+1][0] = r2; b[nxt][2*j2+1][1] = r3;
                }
            }
            #pragma unroll
            for (int i = 0; i < 4; i++)
                #pragma unroll
                for (int j = 0; j < 4; j++)
                    mma_s8(iacc[i][j], a[cur][i][0], a[cur][i][1], a[cur][i][2], a[cur][i][3],
                           b[cur][j][0], b[cur][j][1]);
        }

        // phase boundaries: drain int accum into float accum
        if (kt == 4 || kt == 14 || kt == 29){
            #pragma unroll
            for (int i = 0; i < 4; i++)
                #pragma unroll
                for (int j = 0; j < 4; j++)
                    #pragma unroll
                    for (int r = 0; r < 4; r++){
                        facc[i][j][r] = facc[i][j][r]*128.0f + (float)iacc[i][j][r];
                        iacc[i][j][r] = 0;
                    }
        }
    }

    // epilogue: ts = F * 2^14 * sA * sB + bias   (the 2^14 folds into sA here)
    const int colBase = blockN + wn*32 + 2*(lane & 3);
    float2 bj[4], sB2[4];
    #pragma unroll
    for (int j = 0; j < 4; j++){
        bj[j]  = *(const float2*)(bias + colBase + j*8);
        sB2[j] = *(const float2*)(g_sB + colBase + j*8);
    }
    #pragma unroll
    for (int i = 0; i < 4; i++){
        int row0 = blockM + wm*64 + i*16 + (lane >> 2);
        float sA0 = g_sA[row0] * 16384.0f, sA1 = g_sA[row0 + 8] * 16384.0f;
        float* r0p = g_ts + (size_t)row0 * Nn + colBase;
        float* r1p = r0p + (size_t)8 * Nn;
        #pragma unroll
        for (int j = 0; j < 4; j++){
            float2 v0, v1;
            v0.x = facc[i][j][0]*sA0*sB2[j].x + bj[j].x;
            v0.y = facc[i][j][1]*sA0*sB2[j].y + bj[j].y;
            v1.x = facc[i][j][2]*sA1*sB2[j].x + bj[j].x;
            v1.y = facc[i][j][3]*sA1*sB2[j].y + bj[j].y;
            *(float2*)(r0p + j*8) = v0;
            *(float2*)(r1p + j*8) = v1;
        }
    }
}

// ---------------- 4. max-sum scan (unchanged) ----------------
struct ScanState {
    float hid[7];
    float sc;
};

__device__ __forceinline__ void scan_load(float2* buf, const float2* base, int chunk){
    #pragma unroll
    for (int u = 0; u < 4; u++){
        const float2* q = base + (size_t)(chunk*4 + u) * (Nn/2);
        #pragma unroll
        for (int j = 0; j < 7; j++) buf[u*7 + j] = q[j];
    }
}

__device__ __forceinline__ void scan_step(ScanState& st, const float* f,
                                          const float* eps, bool end5){
    float ae[7];
    ae[0] = st.hid[0];
    #pragma unroll
    for (int m = 1; m < 7; m++) ae[m] = fmaxf(st.hid[m], st.hid[m-1] + eps[m-1]);
    float nh[7];
    nh[0] = fmaxf(0.0f, ae[0] + f[0]);
    #pragma unroll
    for (int m = 1; m < 7; m++)
        nh[m] = fmaxf(ae[m-1] + f[7 + m - 1], ae[m] + f[m]);
    #pragma unroll
    for (int m = 0; m < 7; m++) st.hid[m] = nh[m];
    st.sc = fmaxf(st.sc, end5 ? st.hid[5] : st.hid[6]);
}

__device__ __forceinline__ void scan_compute(ScanState& st, const float2* buf,
                                             const float* eps, bool end5){
    #pragma unroll
    for (int u = 0; u < 4; u++){
        float f[14];
        #pragma unroll
        for (int j = 0; j < 7; j++){ f[2*j] = buf[u*7 + j].x; f[2*j+1] = buf[u*7 + j].y; }
        scan_step(st, f, eps, end5);
    }
}

__global__ __launch_bounds__(64) void scan_kernel(const int* __restrict__ doc_lens,
                                                  const float* __restrict__ epsilons)
{
    int idx = blockIdx.x * 64 + threadIdx.x;
    int b = idx >> 9;
    int p = idx & 511;

    float eps[6];
    #pragma unroll
    for (int i = 0; i < 6; i++) eps[i] = epsilons[p*6 + i];
    const bool end5 = (p < 256);
    const int dl = doc_lens[b];
    const int n4 = dl >> 2, rem = dl & 3;

    ScanState st;
    st.hid[0] = 0.0f;
    #pragma unroll
    for (int m = 1; m < 7; m++) st.hid[m] = NEGV;
    st.sc = NEGV;

    const float2* base = (const float2*)(g_ts + (size_t)g_off[b] * Nn + (size_t)p * 14);

    float2 buf0[28], buf1[28];
    scan_load(buf0, base, 0);

    int c = 0;
    #pragma unroll 1
    while (c + 2 <= n4){
        scan_load(buf1, base, c + 1);
        scan_compute(st, buf0, eps, end5);
        if (c + 2 < n4) scan_load(buf0, base, c + 2);
        scan_compute(st, buf1, eps, end5);
        c += 2;
    }
    if (c < n4){
        scan_compute(st, buf0, eps, end5);
    }
    #pragma unroll 1
    for (int u = 0; u < rem; u++){
        const float2* q = base + (size_t)(n4*4 + u) * (Nn/2);
        float f[14];
        #pragma unroll
        for (int j = 0; j < 7; j++){ float2 v = q[j]; f[2*j] = v.x; f[2*j+1] = v.y; }
        scan_step(st, f, eps, end5);
    }
    g_scores[idx] = st.sc;
}

// ---------------- 5. batchnorm + binarize + final linear ----------------
__global__ __launch_bounds__(512) void final_kernel(const float* __restrict__ bn_w,
                                                    const float* __restrict__ bn_b,
                                                    const float* __restrict__ fw,
                                                    const float* __restrict__ fb,
                                                    float* __restrict__ out)
{
    __shared__ unsigned char sbin[Bb][Pp];
    int p = threadIdx.x;

    float x[Bb];
    float s = 0.0f;
    #pragma unroll
    for (int b = 0; b < Bb; b++){ x[b] = g_scores[b*Pp + p]; s += x[b]; }
    float mean = s * (1.0f / Bb);
    float v = 0.0f;
    #pragma unroll
    for (int b = 0; b < Bb; b++){ float d = x[b] - mean; v += d * d; }
    v *= (1.0f / Bb);
    float inv = rsqrtf(v + 1e-5f);
    float w = bn_w[p], bb = bn_b[p];
    #pragma unroll
    for (int b = 0; b < Bb; b++){
        float y = (x[b] - mean) * inv * w + bb;
        sbin[b][p] = (y > 0.0f) ? 1 : 0;
    }
    __syncthreads();

    int warp = p >> 5, lane = p & 31;
    #pragma unroll
    for (int q = 0; q < 4; q++){
        int o = warp * 4 + q;
        int b = o >> 1, c = o & 1;
        float acc = 0.0f;
        for (int pp = lane; pp < Pp; pp += 32)
            if (sbin[b][pp]) acc += fw[c*Pp + pp];
        #pragma unroll
        for (int off = 16; off > 0; off >>= 1)
            acc += __shfl_xor_sync(0xffffffffu, acc, off);
        if (lane == 0) out[b*NCc + c] = acc + fb[c];
    }
}

// ---------------- host launch ----------------
extern "C" void kernel_launch(void* const* d_in, const int* in_sizes, int n_in,
                              void* d_out, int out_size)
{
    const int*   tokens    = (const int*)  d_in[0];
    const int*   doc_lens  = (const int*)  d_in[1];
    const float* emb_table = (const float*)d_in[2];
    const float* diags     = (const float*)d_in[3];
    const float* bias      = (const float*)d_in[4];
    const float* epsilons  = (const float*)d_in[5];
    const float* bn_weight = (const float*)d_in[6];
    const float* bn_bias   = (const float*)d_in[7];
    const float* final_w   = (const float*)d_in[8];
    const float* final_b   = (const float*)d_in[9];
    float* out = (float*)d_out;

    offsets_kernel<<<1, 32>>>(doc_lens);
    convA_kernel<<<Mm, 128>>>(tokens, emb_table, doc_lens);
    convB_kernel<<<Nn, 128>>>(diags);

    cudaFuncSetAttribute(gemm_kernel, cudaFuncAttributeMaxDynamicSharedMemorySize, SMEM_GEMM);
    dim3 grid(Nn / TILE_N, Mm / TILE_M);   // (56, 32); M-tiles beyond padTo exit
    gemm_kernel<<<grid, 256, SMEM_GEMM>>>(bias);

    scan_kernel<<<(Bb*Pp) / 64, 64>>>(doc_lens, epsilons);
    final_kernel<<<1, 512>>>(bn_weight, bn_bias, final_w, final_b, out);
}

// round 12
// speedup vs baseline: 5.9910x; 5.9910x over previous
#include <cuda_runtime.h>
#include <cuda_bf16.h>
#include <cstdint>

// ---------------- problem constants ----------------
#define Bb    32
#define Tt    128
#define Pp    512
#define MAXL  7
#define Dd    300
#define KSEG  304            // per-segment K (>=300, mult of 16)
#define KP    (4*KSEG)       // 1216 = 19*64
#define NP    6144           // packed N: 256 patterns x 11 + 256 x 13
#define Mm    4096           // B*T (max)
#define NCc   2
#define NEGV  (-1e30f)

// gemm tiling: CTA 128(M) x 256(N), 8 warps (2M x 4N), warp tile 64x64, BK=64
#define TILE_M 128
#define TILE_N 256
#define BK    64
#define NKT   (KP/BK)        // 19
#define NSTG  3
#define ROWB  144            // 128 B data + 16 pad -> conflict-free ldmatrix
#define STAGE_A   (TILE_M*ROWB)          // 18432
#define STAGE_B   (TILE_N*ROWB)          // 36864
#define STAGE_SZ  (STAGE_A+STAGE_B)      // 55296
#define SMEM_GEMM (NSTG*STAGE_SZ)        // 165888
#define CPT 12   // cp.async 16B tasks/thread/stage: 384 rows x 8 chunks / 256 thr

// ---------------- scratch ----------------
__device__ __nv_bfloat16 g_Aq[(size_t)Mm * KP];   // [h,h,m,m], M-compacted
__device__ __nv_bfloat16 g_Bq[(size_t)NP * KP];   // [h,m,h,m], N-packed
__device__ float g_biasP[NP];                     // packed bias
__device__ float g_ts[(size_t)Mm * NP];           // M-compacted, N-packed
__device__ float g_scores[Bb * Pp];

// ---------------- PTX helpers ----------------
__device__ __forceinline__ void cpasync16(uint32_t s, const void* g){
    asm volatile("cp.async.cg.shared.global [%0], [%1], 16;" :: "r"(s), "l"(g));
}
__device__ __forceinline__ void cp_commit(){
    asm volatile("cp.async.commit_group;" ::: "memory");
}
template<int N> __device__ __forceinline__ void cp_wait(){
    asm volatile("cp.async.wait_group %0;" :: "n"(N) : "memory");
}
__device__ __forceinline__ void ldsm4(uint32_t a, uint32_t& r0, uint32_t& r1, uint32_t& r2, uint32_t& r3){
    asm volatile("ldmatrix.sync.aligned.m8n8.x4.shared.b16 {%0,%1,%2,%3}, [%4];"
                 : "=r"(r0), "=r"(r1), "=r"(r2), "=r"(r3) : "r"(a));
}
__device__ __forceinline__ void mma16816(float* c, uint32_t a0, uint32_t a1, uint32_t a2, uint32_t a3,
                                         uint32_t b0, uint32_t b1){
    asm volatile("mma.sync.aligned.m16n8k16.row.col.f32.bf16.bf16.f32 "
                 "{%0,%1,%2,%3}, {%4,%5,%6,%7}, {%8,%9}, {%0,%1,%2,%3};"
                 : "+f"(c[0]), "+f"(c[1]), "+f"(c[2]), "+f"(c[3])
                 : "r"(a0), "r"(a1), "r"(a2), "r"(a3), "r"(b0), "r"(b1));
}

// ---------------- 1. bf16 split conversion of A (gathered embeddings, compacted M) ----------------
__global__ void convA_kernel(const int* __restrict__ tokens, const float* __restrict__ emb,
                             const int* __restrict__ doc_lens){
    int b = blockIdx.x >> 7, t = blockIdx.x & 127;
    if (t >= doc_lens[b]) return;
    int off = 0;
    for (int i = 0; i < b; i++) off += doc_lens[i];     // uniform per block, L1-hit
    int mrow = off + t;
    int tok = tokens[blockIdx.x];
    __nv_bfloat16* row = g_Aq + (size_t)mrow * KP;
    const float* src = emb + (size_t)tok * Dd;
    for (int k = threadIdx.x; k < KSEG; k += blockDim.x){
        float x = (k < Dd) ? src[k] : 0.0f;
        __nv_bfloat16 h = __float2bfloat16(x);
        __nv_bfloat16 m = __float2bfloat16(x - __bfloat162float(h));
        row[0*KSEG + k] = h;  row[1*KSEG + k] = h;
        row[2*KSEG + k] = m;  row[3*KSEG + k] = m;
    }
}

// ---------------- 2. bf16 split conversion of B, packed-N remap ----------------
// packed col n' -> (p,d,m): p<256: n'=p*11 + (d==0 ? m : 6+m), m<=5 / m<=4
//                           p>=256: n'=2816+(p-256)*13 + (d==0 ? m : 7+m), m<=6 / m<=5
// source diags row k = p*14 + d*7 + m
__global__ void convB_kernel(const float* __restrict__ diags, const float* __restrict__ bias){
    int n = blockIdx.x;
    int p, d, m;
    if (n < 2816){
        p = n / 11; int r = n % 11;
        d = (r < 6) ? 0 : 1; m = d ? (r - 6) : r;
    } else {
        int q = n - 2816;
        p = 256 + q / 13; int r = q % 13;
        d = (r < 7) ? 0 : 1; m = d ? (r - 7) : r;
    }
    int k = p*14 + d*7 + m;
    const float* src = diags + (size_t)k * Dd;
    __nv_bfloat16* row = g_Bq + (size_t)n * KP;
    for (int kk = threadIdx.x; kk < KSEG; kk += blockDim.x){
        float x = (kk < Dd) ? src[kk] : 0.0f;
        __nv_bfloat16 h = __float2bfloat16(x);
        __nv_bfloat16 mm = __float2bfloat16(x - __bfloat162float(h));
        row[0*KSEG + kk] = h;   row[1*KSEG + kk] = mm;
        row[2*KSEG + kk] = h;   row[3*KSEG + kk] = mm;
    }
    if (threadIdx.x == 0) g_biasP[n] = bias[k];
}

// ---------------- 3. bf16 mma.sync GEMM (R8 structure, packed N) ----------------
__global__ __launch_bounds__(256, 1) void gemm_kernel(const int* __restrict__ doc_lens)
{
    __shared__ int s_pad;
    if (threadIdx.x == 0){
        int acc = 0;
        for (int i = 0; i < Bb; i++) acc += doc_lens[i];
        s_pad = (acc + TILE_M - 1) & ~(TILE_M - 1);
    }
    __syncthreads();
    const int blockM = blockIdx.y * TILE_M;
    if (blockM >= s_pad) return;

    extern __shared__ char smem[];
    const uint32_t sb = (uint32_t)__cvta_generic_to_shared(smem);
    const int tid = threadIdx.x;
    const int lane = tid & 31, wid = tid >> 5;
    const int wm = wid & 1, wn = wid >> 1;     // 2M x 4N
    const int blockN = blockIdx.x * TILE_N;

    const __nv_bfloat16* gA = g_Aq + (size_t)blockM * KP;
    const __nv_bfloat16* gB = g_Bq + (size_t)blockN * KP;

    // cp.async tasks: 384 rows x 8 x 16B chunks
    uint32_t t_soff[CPT];
    const __nv_bfloat16* t_gptr[CPT];
    #pragma unroll
    for (int q = 0; q < CPT; q++){
        int id = tid + q*256;
        int row = id >> 3, ch = id & 7;
        int isB = (row >= TILE_M);
        int r2  = isB ? (row - TILE_M) : row;
        t_soff[q] = (isB ? STAGE_A : 0) + r2*ROWB + ch*16;
        t_gptr[q] = (isB ? gB : gA) + (size_t)r2 * KP + ch*8;
    }

    const uint32_t aBase = sb + (wm*64 + (lane & 15)) * ROWB + (lane >> 4) * 16;
    const uint32_t bBase = sb + STAGE_A + (wn*64 + ((lane >> 4) << 3) + (lane & 7)) * ROWB
                              + (((lane >> 3) & 1) * 16);

    float acc[4][8][4];
    #pragma unroll
    for (int i = 0; i < 4; i++)
        #pragma unroll
        for (int j = 0; j < 8; j++)
            #pragma unroll
            for (int r = 0; r < 4; r++) acc[i][j][r] = 0.0f;

    #pragma unroll
    for (int s = 0; s < NSTG-1; s++){
        #pragma unroll
        for (int q = 0; q < CPT; q++)
            cpasync16(sb + s*STAGE_SZ + t_soff[q], t_gptr[q] + s*BK);
        cp_commit();
    }

    uint32_t a[2][4][4], b[2][8][2];

    for (int kt = 0; kt < NKT; kt++){
        cp_wait<NSTG-2>();
        __syncthreads();
        const uint32_t stage = (kt % NSTG) * STAGE_SZ;

        #pragma unroll
        for (int i = 0; i < 4; i++)
            ldsm4(aBase + stage + i*16*ROWB, a[0][i][0], a[0][i][1], a[0][i][2], a[0][i][3]);
        #pragma unroll
        for (int j2 = 0; j2 < 4; j2++){
            uint32_t r0, r1, r2, r3;
            ldsm4(bBase + stage + j2*16*ROWB, r0, r1, r2, r3);
            b[0][2*j2][0] = r0;   b[0][2*j2][1] = r1;
            b[0][2*j2+1][0] = r2; b[0][2*j2+1][1] = r3;
        }

        int nkt = kt + NSTG - 1;
        if (nkt < NKT){
            uint32_t stb = sb + (nkt % NSTG)*STAGE_SZ;
            #pragma unroll
            for (int q = 0; q < CPT; q++)
                cpasync16(stb + t_soff[q], t_gptr[q] + nkt*BK);
        }
        cp_commit();

        #pragma unroll
        for (int s = 0; s < 4; s++){
            const int cur = s & 1, nxt = cur ^ 1;
            if (s < 3){
                #pragma unroll
                for (int i = 0; i < 4; i++)
                    ldsm4(aBase + stage + i*16*ROWB + (s+1)*32,
                          a[nxt][i][0], a[nxt][i][1], a[nxt][i][2], a[nxt][i][3]);
                #pragma unroll
                for (int j2 = 0; j2 < 4; j2++){
                    uint32_t r0, r1, r2, r3;
                    ldsm4(bBase + stage + j2*16*ROWB + (s+1)*32, r0, r1, r2, r3);
                    b[nxt][2*j2][0] = r0;   b[nxt][2*j2][1] = r1;
                    b[nxt][2*j2+1][0] = r2; b[nxt][2*j2+1][1] = r3;
                }
            }
            #pragma unroll
            for (int i = 0; i < 4; i++)
                #pragma unroll
                for (int j = 0; j < 8; j++)
                    mma16816(acc[i][j], a[cur][i][0], a[cur][i][1], a[cur][i][2], a[cur][i][3],
                             b[cur][j][0], b[cur][j][1]);
        }
    }

    // epilogue: add packed bias, store float2 pairs
    const int colBase = blockN + wn*64 + 2*(lane & 3);
    #pragma unroll
    for (int i = 0; i < 4; i++){
        int row0 = blockM + wm*64 + i*16 + (lane >> 2);
        float* r0p = g_ts + (size_t)row0 * NP + colBase;
        float* r1p = r0p + (size_t)8 * NP;
        #pragma unroll
        for (int j = 0; j < 8; j++){
            float2 bj = *(const float2*)(g_biasP + colBase + j*8);
            float2 v0 = make_float2(acc[i][j][0] + bj.x, acc[i][j][1] + bj.y);
            float2 v1 = make_float2(acc[i][j][2] + bj.x, acc[i][j][3] + bj.y);
            *(float2*)(r0p + j*8) = v0;
            *(float2*)(r1p + j*8) = v1;
        }
    }
}

// ---------------- 4. max-sum scan, packed columns, 6/7-state variants ----------------
// packed row layout per pattern: [ tm0[0..NST-1] | tm1[0..NST-2] ]  (W = 2*NST-1 floats)
template<int NST>
__device__ __forceinline__ void step_t(float* hid, float& sc, const float* f, const float* eps){
    float ae[NST];
    ae[0] = hid[0];
    #pragma unroll
    for (int m = 1; m < NST; m++) ae[m] = fmaxf(hid[m], hid[m-1] + eps[m-1]);
    float nh[NST];
    nh[0] = fmaxf(0.0f, ae[0] + f[0]);
    #pragma unroll
    for (int m = 1; m < NST; m++)
        nh[m] = fmaxf(ae[m-1] + f[NST + m - 1], ae[m] + f[m]);
    #pragma unroll
    for (int m = 0; m < NST; m++) hid[m] = nh[m];
    sc = fmaxf(sc, hid[NST-1]);
}

template<int NST>
__device__ __forceinline__ void load_t(float* buf, const float* base, int chunk){
    constexpr int W = 2*NST - 1;
    #pragma unroll
    for (int u = 0; u < 4; u++){
        const float* q = base + (size_t)(chunk*4 + u) * NP;
        #pragma unroll
        for (int j = 0; j < W; j++) buf[u*W + j] = q[j];
    }
}

template<int NST>
__device__ __forceinline__ void comp_t(float* hid, float& sc, const float* buf, const float* eps){
    constexpr int W = 2*NST - 1;
    #pragma unroll
    for (int u = 0; u < 4; u++) step_t<NST>(hid, sc, buf + u*W, eps);
}

template<int NST>
__device__ __forceinline__ float scan_run(const float* base, int dl, const float* eps){
    constexpr int W = 2*NST - 1;
    float hid[NST];
    hid[0] = 0.0f;
    #pragma unroll
    for (int m = 1; m < NST; m++) hid[m] = NEGV;
    float sc = NEGV;
    const int n4 = dl >> 2, rem = dl & 3;

    float buf0[4*W], buf1[4*W];
    load_t<NST>(buf0, base, 0);

    int c = 0;
    #pragma unroll 1
    while (c + 2 <= n4){
        load_t<NST>(buf1, base, c + 1);
        comp_t<NST>(hid, sc, buf0, eps);
        if (c + 2 < n4) load_t<NST>(buf0, base, c + 2);
        comp_t<NST>(hid, sc, buf1, eps);
        c += 2;
    }
    if (c < n4) comp_t<NST>(hid, sc, buf0, eps);
    #pragma unroll 1
    for (int u = 0; u < rem; u++){
        const float* q = base + (size_t)(n4*4 + u) * NP;
        float f[W];
        #pragma unroll
        for (int j = 0; j < W; j++) f[j] = q[j];
        step_t<NST>(hid, sc, f, eps);
    }
    return sc;
}

__global__ __launch_bounds__(64) void scan_kernel(const int* __restrict__ doc_lens,
                                                  const float* __restrict__ epsilons)
{
    int idx = blockIdx.x * 64 + threadIdx.x;
    int b = idx >> 9;
    int p = idx & 511;

    float eps[6];
    #pragma unroll
    for (int i = 0; i < 6; i++) eps[i] = epsilons[p*6 + i];
    const int dl = doc_lens[b];
    int off = 0;
    for (int i = 0; i < b; i++) off += doc_lens[i];    // uniform per block

    float sc;
    if (p < 256){      // length-6 patterns: 6 live states, 11 packed cols
        const float* base = g_ts + (size_t)off * NP + p*11;
        sc = scan_run<6>(base, dl, eps);
    } else {           // length-7 patterns: 7 states, 13 packed cols
        const float* base = g_ts + (size_t)off * NP + 2816 + (p - 256)*13;
        sc = scan_run<7>(base, dl, eps);
    }
    g_scores[idx] = sc;
}

// ---------------- 5. batchnorm + binarize + final linear ----------------
__global__ __launch_bounds__(512) void final_kernel(const float* __restrict__ bn_w,
                                                    const float* __restrict__ bn_b,
                                                    const float* __restrict__ fw,
                                                    const float* __restrict__ fb,
                                                    float* __restrict__ out)
{
    __shared__ unsigned char sbin[Bb][Pp];
    int p = threadIdx.x;

    float x[Bb];
    float s = 0.0f;
    #pragma unroll
    for (int b = 0; b < Bb; b++){ x[b] = g_scores[b*Pp + p]; s += x[b]; }
    float mean = s * (1.0f / Bb);
    float v = 0.0f;
    #pragma unroll
    for (int b = 0; b < Bb; b++){ float d = x[b] - mean; v += d * d; }
    v *= (1.0f / Bb);
    float inv = rsqrtf(v + 1e-5f);
    float w = bn_w[p], bb = bn_b[p];
    #pragma unroll
    for (int b = 0; b < Bb; b++){
        float y = (x[b] - mean) * inv * w + bb;
        sbin[b][p] = (y > 0.0f) ? 1 : 0;
    }
    __syncthreads();

    int warp = p >> 5, lane = p & 31;
    #pragma unroll
    for (int q = 0; q < 4; q++){
        int o = warp * 4 + q;
        int b = o >> 1, c = o & 1;
        float acc = 0.0f;
        for (int pp = lane; pp < Pp; pp += 32)
            if (sbin[b][pp]) acc += fw[c*Pp + pp];
        #pragma unroll
        for (int off = 16; off > 0; off >>= 1)
            acc += __shfl_xor_sync(0xffffffffu, acc, off);
        if (lane == 0) out[b*NCc + c] = acc + fb[c];
    }
}

// ---------------- host launch ----------------
extern "C" void kernel_launch(void* const* d_in, const int* in_sizes, int n_in,
                              void* d_out, int out_size)
{
    const int*   tokens    = (const int*)  d_in[0];
    const int*   doc_lens  = (const int*)  d_in[1];
    const float* emb_table = (const float*)d_in[2];
    const float* diags     = (const float*)d_in[3];
    const float* bias      = (const float*)d_in[4];
    const float* epsilons  = (const float*)d_in[5];
    const float* bn_weight = (const float*)d_in[6];
    const float* bn_bias   = (const float*)d_in[7];
    const float* final_w   = (const float*)d_in[8];
    const float* final_b   = (const float*)d_in[9];
    float* out = (float*)d_out;

    convA_kernel<<<Mm, 128>>>(tokens, emb_table, doc_lens);
    convB_kernel<<<NP, 128>>>(diags, bias);

    cudaFuncSetAttribute(gemm_kernel, cudaFuncAttributeMaxDynamicSharedMemorySize, SMEM_GEMM);
    dim3 grid(NP / TILE_N, Mm / TILE_M);   // (24, 32); M-tiles beyond padTo exit
    gemm_kernel<<<grid, 256, SMEM_GEMM>>>(doc_lens);

    scan_kernel<<<(Bb*Pp) / 64, 64>>>(doc_lens, epsilons);
    final_kernel<<<1, 512>>>(bn_weight, bn_bias, final_w, final_b, out);
}

// round 13
// speedup vs baseline: 6.9652x; 1.1626x over previous
#include <cuda_runtime.h>
#include <cuda_bf16.h>
#include <cstdint>

// ---------------- problem constants ----------------
#define Bb    32
#define Tt    128
#define Pp    512
#define MAXL  7
#define Dd    300
#define KSEG  320            // per-segment K (>=300, mult of 64/3-friendly)
#define KP    (3*KSEG)       // 960 = 15*64 ; segments A=[h,h,m], B=[h,m,h]
#define NP    6144           // packed N: 256 patterns x 11 + 256 x 13
#define Mm    4096           // B*T (max)
#define NCc   2
#define NEGV  (-1e30f)

// gemm tiling: CTA 128(M) x 256(N), 8 warps (2M x 4N), warp tile 64x64, BK=64
#define TILE_M 128
#define TILE_N 256
#define BK    64
#define NKT   (KP/BK)        // 15
#define NSTG  3
#define ROWB  144            // 128 B data + 16 pad -> conflict-free ldmatrix
#define STAGE_A   (TILE_M*ROWB)          // 18432
#define STAGE_B   (TILE_N*ROWB)          // 36864
#define STAGE_SZ  (STAGE_A+STAGE_B)      // 55296
#define SMEM_GEMM (NSTG*STAGE_SZ)        // 165888
#define CPT 12   // cp.async 16B tasks/thread/stage: 384 rows x 8 chunks / 256 thr

// ---------------- scratch ----------------
__device__ __nv_bfloat16 g_Aq[(size_t)Mm * KP];   // [h,h,m], M-compacted
__device__ __nv_bfloat16 g_Bq[(size_t)NP * KP];   // [h,m,h], N-packed
__device__ float g_biasP[NP];                     // packed bias
__device__ float g_ts[(size_t)Mm * NP];           // M-compacted, N-packed
__device__ float g_scores[Bb * Pp];

// ---------------- PTX helpers ----------------
__device__ __forceinline__ void cpasync16(uint32_t s, const void* g){
    asm volatile("cp.async.cg.shared.global [%0], [%1], 16;" :: "r"(s), "l"(g));
}
__device__ __forceinline__ void cp_commit(){
    asm volatile("cp.async.commit_group;" ::: "memory");
}
template<int N> __device__ __forceinline__ void cp_wait(){
    asm volatile("cp.async.wait_group %0;" :: "n"(N) : "memory");
}
__device__ __forceinline__ void ldsm4(uint32_t a, uint32_t& r0, uint32_t& r1, uint32_t& r2, uint32_t& r3){
    asm volatile("ldmatrix.sync.aligned.m8n8.x4.shared.b16 {%0,%1,%2,%3}, [%4];"
                 : "=r"(r0), "=r"(r1), "=r"(r2), "=r"(r3) : "r"(a));
}
__device__ __forceinline__ void mma16816(float* c, uint32_t a0, uint32_t a1, uint32_t a2, uint32_t a3,
                                         uint32_t b0, uint32_t b1){
    asm volatile("mma.sync.aligned.m16n8k16.row.col.f32.bf16.bf16.f32 "
                 "{%0,%1,%2,%3}, {%4,%5,%6,%7}, {%8,%9}, {%0,%1,%2,%3};"
                 : "+f"(c[0]), "+f"(c[1]), "+f"(c[2]), "+f"(c[3])
                 : "r"(a0), "r"(a1), "r"(a2), "r"(a3), "r"(b0), "r"(b1));
}

// ---------------- 1. bf16 split conversion of A (gathered embeddings, compacted M) ----------------
__global__ void convA_kernel(const int* __restrict__ tokens, const float* __restrict__ emb,
                             const int* __restrict__ doc_lens){
    int b = blockIdx.x >> 7, t = blockIdx.x & 127;
    if (t >= doc_lens[b]) return;
    int off = 0;
    for (int i = 0; i < b; i++) off += doc_lens[i];     // uniform per block, L1-hit
    int mrow = off + t;
    int tok = tokens[blockIdx.x];
    __nv_bfloat16* row = g_Aq + (size_t)mrow * KP;
    const float* src = emb + (size_t)tok * Dd;
    for (int k = threadIdx.x; k < KSEG; k += blockDim.x){
        float x = (k < Dd) ? src[k] : 0.0f;
        __nv_bfloat16 h = __float2bfloat16(x);
        __nv_bfloat16 m = __float2bfloat16(x - __bfloat162float(h));
        row[0*KSEG + k] = h;  row[1*KSEG + k] = h;  row[2*KSEG + k] = m;
    }
}

// ---------------- 2. bf16 split conversion of B, packed-N remap ----------------
// packed col n' -> (p,d,m): p<256: n'=p*11 + (d==0 ? m : 6+m)
//                           p>=256: n'=2816+(p-256)*13 + (d==0 ? m : 7+m)
// source diags row k = p*14 + d*7 + m
__global__ void convB_kernel(const float* __restrict__ diags, const float* __restrict__ bias){
    int n = blockIdx.x;
    int p, d, m;
    if (n < 2816){
        p = n / 11; int r = n % 11;
        d = (r < 6) ? 0 : 1; m = d ? (r - 6) : r;
    } else {
        int q = n - 2816;
        p = 256 + q / 13; int r = q % 13;
        d = (r < 7) ? 0 : 1; m = d ? (r - 7) : r;
    }
    int k = p*14 + d*7 + m;
    const float* src = diags + (size_t)k * Dd;
    __nv_bfloat16* row = g_Bq + (size_t)n * KP;
    for (int kk = threadIdx.x; kk < KSEG; kk += blockDim.x){
        float x = (kk < Dd) ? src[kk] : 0.0f;
        __nv_bfloat16 h = __float2bfloat16(x);
        __nv_bfloat16 mm = __float2bfloat16(x - __bfloat162float(h));
        row[0*KSEG + kk] = h;   row[1*KSEG + kk] = mm;  row[2*KSEG + kk] = h;
    }
    if (threadIdx.x == 0) g_biasP[n] = bias[k];
}

// ---------------- 3. bf16 mma.sync GEMM (R8 structure, packed N, K=960) ----------------
__global__ __launch_bounds__(256, 1) void gemm_kernel(const int* __restrict__ doc_lens)
{
    __shared__ int s_pad;
    if (threadIdx.x == 0){
        int acc = 0;
        for (int i = 0; i < Bb; i++) acc += doc_lens[i];
        s_pad = (acc + TILE_M - 1) & ~(TILE_M - 1);
    }
    __syncthreads();
    const int blockM = blockIdx.y * TILE_M;
    if (blockM >= s_pad) return;

    extern __shared__ char smem[];
    const uint32_t sb = (uint32_t)__cvta_generic_to_shared(smem);
    const int tid = threadIdx.x;
    const int lane = tid & 31, wid = tid >> 5;
    const int wm = wid & 1, wn = wid >> 1;     // 2M x 4N
    const int blockN = blockIdx.x * TILE_N;

    const __nv_bfloat16* gA = g_Aq + (size_t)blockM * KP;
    const __nv_bfloat16* gB = g_Bq + (size_t)blockN * KP;

    // cp.async tasks: 384 rows x 8 x 16B chunks
    uint32_t t_soff[CPT];
    const __nv_bfloat16* t_gptr[CPT];
    #pragma unroll
    for (int q = 0; q < CPT; q++){
        int id = tid + q*256;
        int row = id >> 3, ch = id & 7;
        int isB = (row >= TILE_M);
        int r2  = isB ? (row - TILE_M) : row;
        t_soff[q] = (isB ? STAGE_A : 0) + r2*ROWB + ch*16;
        t_gptr[q] = (isB ? gB : gA) + (size_t)r2 * KP + ch*8;
    }

    const uint32_t aBase = sb + (wm*64 + (lane & 15)) * ROWB + (lane >> 4) * 16;
    const uint32_t bBase = sb + STAGE_A + (wn*64 + ((lane >> 4) << 3) + (lane & 7)) * ROWB
                              + (((lane >> 3) & 1) * 16);

    float acc[4][8][4];
    #pragma unroll
    for (int i = 0; i < 4; i++)
        #pragma unroll
        for (int j = 0; j < 8; j++)
            #pragma unroll
            for (int r = 0; r < 4; r++) acc[i][j][r] = 0.0f;

    #pragma unroll
    for (int s = 0; s < NSTG-1; s++){
        #pragma unroll
        for (int q = 0; q < CPT; q++)
            cpasync16(sb + s*STAGE_SZ + t_soff[q], t_gptr[q] + s*BK);
        cp_commit();
    }

    uint32_t a[2][4][4], b[2][8][2];

    for (int kt = 0; kt < NKT; kt++){
        cp_wait<NSTG-2>();
        __syncthreads();
        const uint32_t stage = (kt % NSTG) * STAGE_SZ;

        #pragma unroll
        for (int i = 0; i < 4; i++)
            ldsm4(aBase + stage + i*16*ROWB, a[0][i][0], a[0][i][1], a[0][i][2], a[0][i][3]);
        #pragma unroll
        for (int j2 = 0; j2 < 4; j2++){
            uint32_t r0, r1, r2, r3;
            ldsm4(bBase + stage + j2*16*ROWB, r0, r1, r2, r3);
            b[0][2*j2][0] = r0;   b[0][2*j2][1] = r1;
            b[0][2*j2+1][0] = r2; b[0][2*j2+1][1] = r3;
        }

        int nkt = kt + NSTG - 1;
        if (nkt < NKT){
            uint32_t stb = sb + (nkt % NSTG)*STAGE_SZ;
            #pragma unroll
            for (int q = 0; q < CPT; q++)
                cpasync16(stb + t_soff[q], t_gptr[q] + nkt*BK);
        }
        cp_commit();

        #pragma unroll
        for (int s = 0; s < 4; s++){
            const int cur = s & 1, nxt = cur ^ 1;
            if (s < 3){
                #pragma unroll
                for (int i = 0; i < 4; i++)
                    ldsm4(aBase + stage + i*16*ROWB + (s+1)*32,
                          a[nxt][i][0], a[nxt][i][1], a[nxt][i][2], a[nxt][i][3]);
                #pragma unroll
                for (int j2 = 0; j2 < 4; j2++){
                    uint32_t r0, r1, r2, r3;
                    ldsm4(bBase + stage + j2*16*ROWB + (s+1)*32, r0, r1, r2, r3);
                    b[nxt][2*j2][0] = r0;   b[nxt][2*j2][1] = r1;
                    b[nxt][2*j2+1][0] = r2; b[nxt][2*j2+1][1] = r3;
                }
            }
            #pragma unroll
            for (int i = 0; i < 4; i++)
                #pragma unroll
                for (int j = 0; j < 8; j++)
                    mma16816(acc[i][j], a[cur][i][0], a[cur][i][1], a[cur][i][2], a[cur][i][3],
                             b[cur][j][0], b[cur][j][1]);
        }
    }

    // epilogue: add packed bias, store float2 pairs
    const int colBase = blockN + wn*64 + 2*(lane & 3);
    #pragma unroll
    for (int i = 0; i < 4; i++){
        int row0 = blockM + wm*64 + i*16 + (lane >> 2);
        float* r0p = g_ts + (size_t)row0 * NP + colBase;
        float* r1p = r0p + (size_t)8 * NP;
        #pragma unroll
        for (int j = 0; j < 8; j++){
            float2 bj = *(const float2*)(g_biasP + colBase + j*8);
            float2 v0 = make_float2(acc[i][j][0] + bj.x, acc[i][j][1] + bj.y);
            float2 v1 = make_float2(acc[i][j][2] + bj.x, acc[i][j][3] + bj.y);
            *(float2*)(r0p + j*8) = v0;
            *(float2*)(r1p + j*8) = v1;
        }
    }
}

// ---------------- 4. max-sum scan, packed columns, 6/7-state variants ----------------
template<int NST>
__device__ __forceinline__ void step_t(float* hid, float& sc, const float* f, const float* eps){
    float ae[NST];
    ae[0] = hid[0];
    #pragma unroll
    for (int m = 1; m < NST; m++) ae[m] = fmaxf(hid[m], hid[m-1] + eps[m-1]);
    float nh[NST];
    nh[0] = fmaxf(0.0f, ae[0] + f[0]);
    #pragma unroll
    for (int m = 1; m < NST; m++)
        nh[m] = fmaxf(ae[m-1] + f[NST + m - 1], ae[m] + f[m]);
    #pragma unroll
    for (int m = 0; m < NST; m++) hid[m] = nh[m];
    sc = fmaxf(sc, hid[NST-1]);
}

template<int NST>
__device__ __forceinline__ void load_t(float* buf, const float* base, int chunk){
    constexpr int W = 2*NST - 1;
    #pragma unroll
    for (int u = 0; u < 4; u++){
        const float* q = base + (size_t)(chunk*4 + u) * NP;
        #pragma unroll
        for (int j = 0; j < W; j++) buf[u*W + j] = q[j];
    }
}

template<int NST>
__device__ __forceinline__ void comp_t(float* hid, float& sc, const float* buf, const float* eps){
    constexpr int W = 2*NST - 1;
    #pragma unroll
    for (int u = 0; u < 4; u++) step_t<NST>(hid, sc, buf + u*W, eps);
}

template<int NST>
__device__ __forceinline__ float scan_run(const float* base, int dl, const float* eps){
    constexpr int W = 2*NST - 1;
    float hid[NST];
    hid[0] = 0.0f;
    #pragma unroll
    for (int m = 1; m < NST; m++) hid[m] = NEGV;
    float sc = NEGV;
    const int n4 = dl >> 2, rem = dl & 3;

    float buf0[4*W], buf1[4*W];
    load_t<NST>(buf0, base, 0);

    int c = 0;
    #pragma unroll 1
    while (c + 2 <= n4){
        load_t<NST>(buf1, base, c + 1);
        comp_t<NST>(hid, sc, buf0, eps);
        if (c + 2 < n4) load_t<NST>(buf0, base, c + 2);
        comp_t<NST>(hid, sc, buf1, eps);
        c += 2;
    }
    if (c < n4) comp_t<NST>(hid, sc, buf0, eps);
    #pragma unroll 1
    for (int u = 0; u < rem; u++){
        const float* q = base + (size_t)(n4*4 + u) * NP;
        float f[W];
        #pragma unroll
        for (int j = 0; j < W; j++) f[j] = q[j];
        step_t<NST>(hid, sc, f, eps);
    }
    return sc;
}

__global__ __launch_bounds__(64) void scan_kernel(const int* __restrict__ doc_lens,
                                                  const float* __restrict__ epsilons)
{
    int idx = blockIdx.x * 64 + threadIdx.x;
    int b = idx >> 9;
    int p = idx & 511;

    float eps[6];
    #pragma unroll
    for (int i = 0; i < 6; i++) eps[i] = epsilons[p*6 + i];
    const int dl = doc_lens[b];
    int off = 0;
    for (int i = 0; i < b; i++) off += doc_lens[i];    // uniform per block

    float sc;
    if (p < 256){      // length-6 patterns: 6 live states, 11 packed cols
        const float* base = g_ts + (size_t)off * NP + p*11;
        sc = scan_run<6>(base, dl, eps);
    } else {           // length-7 patterns: 7 states, 13 packed cols
        const float* base = g_ts + (size_t)off * NP + 2816 + (p - 256)*13;
        sc = scan_run<7>(base, dl, eps);
    }
    g_scores[idx] = sc;
}

// ---------------- 5. batchnorm + binarize + final linear ----------------
__global__ __launch_bounds__(512) void final_kernel(const float* __restrict__ bn_w,
                                                    const float* __restrict__ bn_b,
                                                    const float* __restrict__ fw,
                                                    const float* __restrict__ fb,
                                                    float* __restrict__ out)
{
    __shared__ unsigned char sbin[Bb][Pp];
    int p = threadIdx.x;

    float x[Bb];
    float s = 0.0f;
    #pragma unroll
    for (int b = 0; b < Bb; b++){ x[b] = g_scores[b*Pp + p]; s += x[b]; }
    float mean = s * (1.0f / Bb);
    float v = 0.0f;
    #pragma unroll
    for (int b = 0; b < Bb; b++){ float d = x[b] - mean; v += d * d; }
    v *= (1.0f / Bb);
    float inv = rsqrtf(v + 1e-5f);
    float w = bn_w[p], bb = bn_b[p];
    #pragma unroll
    for (int b = 0; b < Bb; b++){
        float y = (x[b] - mean) * inv * w + bb;
        sbin[b][p] = (y > 0.0f) ? 1 : 0;
    }
    __syncthreads();

    int warp = p >> 5, lane = p & 31;
    #pragma unroll
    for (int q = 0; q < 4; q++){
        int o = warp * 4 + q;
        int b = o >> 1, c = o & 1;
        float acc = 0.0f;
        for (int pp = lane; pp < Pp; pp += 32)
            if (sbin[b][pp]) acc += fw[c*Pp + pp];
        #pragma unroll
        for (int off = 16; off > 0; off >>= 1)
            acc += __shfl_xor_sync(0xffffffffu, acc, off);
        if (lane == 0) out[b*NCc + c] = acc + fb[c];
    }
}

// ---------------- host launch ----------------
extern "C" void kernel_launch(void* const* d_in, const int* in_sizes, int n_in,
                              void* d_out, int out_size)
{
    const int*   tokens    = (const int*)  d_in[0];
    const int*   doc_lens  = (const int*)  d_in[1];
    const float* emb_table = (const float*)d_in[2];
    const float* diags     = (const float*)d_in[3];
    const float* bias      = (const float*)d_in[4];
    const float* epsilons  = (const float*)d_in[5];
    const float* bn_weight = (const float*)d_in[6];
    const float* bn_bias   = (const float*)d_in[7];
    const float* final_w   = (const float*)d_in[8];
    const float* final_b   = (const float*)d_in[9];
    float* out = (float*)d_out;

    convA_kernel<<<Mm, 128>>>(tokens, emb_table, doc_lens);
    convB_kernel<<<NP, 128>>>(diags, bias);

    cudaFuncSetAttribute(gemm_kernel, cudaFuncAttributeMaxDynamicSharedMemorySize, SMEM_GEMM);
    dim3 grid(NP / TILE_N, Mm / TILE_M);   // (24, 32); M-tiles beyond padTo exit
    gemm_kernel<<<grid, 256, SMEM_GEMM>>>(doc_lens);

    scan_kernel<<<(Bb*Pp) / 64, 64>>>(doc_lens, epsilons);
    final_kernel<<<1, 512>>>(bn_weight, bn_bias, final_w, final_b, out);
}